// round 3
// baseline (speedup 1.0000x reference)
#include <cuda_runtime.h>
#include <math_constants.h>

#define BATCH 4
#define SEQ   2048
#define DMODEL 1024
#define HDIM  64

// Scratch for the projected q (= k = v). 4*2048*64 floats = 2M floats = 8MB.
__device__ float g_q[BATCH * SEQ * HDIM];

// ---------------------------------------------------------------------------
// Projection: q[m][n] = sum_k x[m][k] * Wq[n][k]
// M = BATCH*SEQ = 8192, N = HDIM = 64, K = DMODEL = 1024.
// Block: 64(M) x 64(N) tile, BK=32, 256 threads, 4x4 register tile each.
// ---------------------------------------------------------------------------
__global__ __launch_bounds__(256) void proj_kernel(const float* __restrict__ x,
                                                   const float* __restrict__ w)
{
    __shared__ float Xs[64][33];
    __shared__ float Ws[64][33];

    const int m0  = blockIdx.x * 64;
    const int tid = threadIdx.x;
    const int ty  = tid >> 4;   // 0..15
    const int tx  = tid & 15;   // 0..15

    float c[4][4] = {};

    for (int kt = 0; kt < DMODEL; kt += 32) {
        // Load 64x32 tile of X and 64x32 tile of W (float4, coalesced)
        {
            const int r  = tid >> 3;        // 0..31
            const int kc = (tid & 7) << 2;  // 0,4,...,28
            #pragma unroll
            for (int h = 0; h < 2; ++h) {
                const int m = r + h * 32;
                float4 vx = *(const float4*)(x + (size_t)(m0 + m) * DMODEL + kt + kc);
                Xs[m][kc + 0] = vx.x; Xs[m][kc + 1] = vx.y;
                Xs[m][kc + 2] = vx.z; Xs[m][kc + 3] = vx.w;
                float4 vw = *(const float4*)(w + (size_t)m * DMODEL + kt + kc);
                Ws[m][kc + 0] = vw.x; Ws[m][kc + 1] = vw.y;
                Ws[m][kc + 2] = vw.z; Ws[m][kc + 3] = vw.w;
            }
        }
        __syncthreads();

        #pragma unroll 16
        for (int k = 0; k < 32; ++k) {
            float a[4], b[4];
            #pragma unroll
            for (int i = 0; i < 4; ++i) a[i] = Xs[ty * 4 + i][k];
            #pragma unroll
            for (int i = 0; i < 4; ++i) b[i] = Ws[tx * 4 + i][k];
            #pragma unroll
            for (int i = 0; i < 4; ++i)
                #pragma unroll
                for (int j = 0; j < 4; ++j)
                    c[i][j] = fmaf(a[i], b[j], c[i][j]);
        }
        __syncthreads();
    }

    #pragma unroll
    for (int i = 0; i < 4; ++i)
        #pragma unroll
        for (int j = 0; j < 4; ++j)
            g_q[(size_t)(m0 + ty * 4 + i) * HDIM + tx * 4 + j] = c[i][j];
}

// ---------------------------------------------------------------------------
// Causal flash attention with q = k = v.
// Block = 64 query rows; iterate KV tiles of 64 (0..rowBlock inclusive).
// Per-thread 4x4 tiles; online softmax; V tile == K tile (same data).
// grid = (SEQ/64, BATCH), 256 threads. Heavy row-blocks launched first.
// ---------------------------------------------------------------------------
__global__ __launch_bounds__(256) void attn_kernel(float* __restrict__ out)
{
    const int bRow  = (int)gridDim.x - 1 - (int)blockIdx.x; // heavy blocks first
    const int batch = blockIdx.y;
    const float* qb = g_q + (size_t)batch * SEQ * HDIM;

    __shared__ float Qs[64][65];
    __shared__ float Ks[64][65];
    __shared__ float Ps[64][65];

    const int tid = threadIdx.x;
    const int ty  = tid >> 4;   // 0..15
    const int tx  = tid & 15;   // 0..15

    // Load Q tile (64x64) — fully coalesced float4
    #pragma unroll
    for (int it = 0; it < 4; ++it) {
        const int f = tid + it * 256;       // float4 index 0..1023
        const int r = f >> 4;               // 0..63
        const int c = (f & 15) << 2;        // 0..60
        float4 v = *(const float4*)(qb + (size_t)(bRow * 64 + r) * HDIM + c);
        Qs[r][c + 0] = v.x; Qs[r][c + 1] = v.y;
        Qs[r][c + 2] = v.z; Qs[r][c + 3] = v.w;
    }

    float mrow[4], lrow[4], o[4][4] = {};
    #pragma unroll
    for (int i = 0; i < 4; ++i) { mrow[i] = -CUDART_INF_F; lrow[i] = 0.0f; }

    const float scale = 0.03125f;  // 1/sqrt(1024)

    for (int kt = 0; kt <= bRow; ++kt) {
        __syncthreads();  // previous PV done reading Ks/Ps
        // Load K (=V) tile
        #pragma unroll
        for (int it = 0; it < 4; ++it) {
            const int f = tid + it * 256;
            const int r = f >> 4;
            const int c = (f & 15) << 2;
            float4 v = *(const float4*)(qb + (size_t)(kt * 64 + r) * HDIM + c);
            Ks[r][c + 0] = v.x; Ks[r][c + 1] = v.y;
            Ks[r][c + 2] = v.z; Ks[r][c + 3] = v.w;
        }
        __syncthreads();

        // S = Q @ K^T  (4x4 per thread)
        float s[4][4] = {};
        #pragma unroll 16
        for (int k = 0; k < 64; ++k) {
            float a[4], b[4];
            #pragma unroll
            for (int i = 0; i < 4; ++i) a[i] = Qs[ty * 4 + i][k];
            #pragma unroll
            for (int i = 0; i < 4; ++i) b[i] = Ks[tx * 4 + i][k];
            #pragma unroll
            for (int i = 0; i < 4; ++i)
                #pragma unroll
                for (int j = 0; j < 4; ++j)
                    s[i][j] = fmaf(a[i], b[j], s[i][j]);
        }

        // scale + causal mask (only the diagonal tile needs masking)
        if (kt == bRow) {
            #pragma unroll
            for (int i = 0; i < 4; ++i)
                #pragma unroll
                for (int j = 0; j < 4; ++j)
                    s[i][j] = (tx * 4 + j > ty * 4 + i) ? -CUDART_INF_F
                                                        : s[i][j] * scale;
        } else {
            #pragma unroll
            for (int i = 0; i < 4; ++i)
                #pragma unroll
                for (int j = 0; j < 4; ++j)
                    s[i][j] *= scale;
        }

        // Online softmax. Each logical row is spread over 16 lanes (same ty).
        float rm[4], rs[4], alpha[4];
        #pragma unroll
        for (int i = 0; i < 4; ++i) {
            rm[i] = fmaxf(fmaxf(s[i][0], s[i][1]), fmaxf(s[i][2], s[i][3]));
            #pragma unroll
            for (int off = 8; off > 0; off >>= 1)
                rm[i] = fmaxf(rm[i], __shfl_xor_sync(0xffffffffu, rm[i], off, 16));
            const float mn = fmaxf(mrow[i], rm[i]);
            alpha[i] = __expf(mrow[i] - mn);   // 0 if mrow was -inf
            mrow[i]  = mn;
        }
        #pragma unroll
        for (int i = 0; i < 4; ++i) {
            rs[i] = 0.0f;
            #pragma unroll
            for (int j = 0; j < 4; ++j) {
                s[i][j] = __expf(s[i][j] - mrow[i]);  // exp(-inf)=0 handles mask
                rs[i] += s[i][j];
            }
            #pragma unroll
            for (int off = 8; off > 0; off >>= 1)
                rs[i] += __shfl_xor_sync(0xffffffffu, rs[i], off, 16);
            lrow[i] = lrow[i] * alpha[i] + rs[i];
            #pragma unroll
            for (int j = 0; j < 4; ++j) o[i][j] *= alpha[i];
        }

        // Stage P to shared
        #pragma unroll
        for (int i = 0; i < 4; ++i)
            #pragma unroll
            for (int j = 0; j < 4; ++j)
                Ps[ty * 4 + i][tx * 4 + j] = s[i][j];
        __syncthreads();

        // O += P @ V   (V == Ks, layout [key][dim])
        #pragma unroll 16
        for (int k = 0; k < 64; ++k) {
            float a[4], b[4];
            #pragma unroll
            for (int i = 0; i < 4; ++i) a[i] = Ps[ty * 4 + i][k];
            #pragma unroll
            for (int j = 0; j < 4; ++j) b[j] = Ks[k][tx * 4 + j];
            #pragma unroll
            for (int i = 0; i < 4; ++i)
                #pragma unroll
                for (int j = 0; j < 4; ++j)
                    o[i][j] = fmaf(a[i], b[j], o[i][j]);
        }
    }

    // Epilogue: normalize and store
    #pragma unroll
    for (int i = 0; i < 4; ++i) {
        const float inv = 1.0f / lrow[i];
        const size_t row = (size_t)batch * SEQ + bRow * 64 + ty * 4 + i;
        #pragma unroll
        for (int j = 0; j < 4; ++j)
            out[row * HDIM + tx * 4 + j] = o[i][j] * inv;
    }
}

extern "C" void kernel_launch(void* const* d_in, const int* in_sizes, int n_in,
                              void* d_out, int out_size)
{
    const float* x  = (const float*)d_in[0];   // [B, L, D] fp32
    const float* Wq = (const float*)d_in[1];   // [H, D] fp32
    float* out = (float*)d_out;                // [B, L, H] fp32

    proj_kernel<<<(BATCH * SEQ) / 64, 256>>>(x, Wq);
    dim3 grid(SEQ / 64, BATCH);
    attn_kernel<<<grid, 256>>>(out);
}

// round 4
// speedup vs baseline: 2.1200x; 2.1200x over previous
#include <cuda_runtime.h>
#include <math_constants.h>

#define BATCH  4
#define SEQ    2048
#define DMODEL 1024
#define HDIM   64

// Scratch for the projected q (= k = v). 4*2048*64 floats = 8MB.
__device__ float g_q[BATCH * SEQ * HDIM];

// ---------------------------------------------------------------------------
// Projection: q[m][n] = sum_k x[m][k] * Wq[n][k]
// M = 8192, N = 64, K = 1024. BM=32, BK=64, 256 threads, grid = 256 CTAs.
// Warp w owns rows 4w..4w+3 (uniform across lanes); lane l owns cols {l, l+32}.
// A-frag: uniform LDS.128 (broadcast). B-frag: LDS.128 at 68-float stride
// (odd multiple of 16B -> conflict-free, 16B-aligned every row).
// ---------------------------------------------------------------------------
__global__ __launch_bounds__(256) void proj_kernel(const float* __restrict__ x,
                                                   const float* __restrict__ wq)
{
    __shared__ float Xs[32][68];
    __shared__ float Wsm[64][68];

    const int m0  = blockIdx.x * 32;
    const int tid = threadIdx.x;
    const int w   = tid >> 5;   // warp 0..7 -> rows 4w..4w+3
    const int l   = tid & 31;   // lane -> cols {l, l+32}

    float c[4][2] = {};

    for (int kt = 0; kt < DMODEL; kt += 64) {
        __syncthreads();
        // Load X tile 32x64 (512 float4, 2 per thread, coalesced)
        #pragma unroll
        for (int u = 0; u < 2; ++u) {
            const int f = u * 256 + tid;     // 0..511
            const int r = f >> 4;            // 0..31
            const int cc = (f & 15) << 2;    // 0..60
            float4 v = *(const float4*)(x + (size_t)(m0 + r) * DMODEL + kt + cc);
            *(float4*)&Xs[r][cc] = v;
        }
        // Load W tile 64x64 (1024 float4, 4 per thread)
        #pragma unroll
        for (int u = 0; u < 4; ++u) {
            const int f = u * 256 + tid;     // 0..1023
            const int r = f >> 4;            // 0..63
            const int cc = (f & 15) << 2;
            float4 v = *(const float4*)(wq + (size_t)r * DMODEL + kt + cc);
            *(float4*)&Wsm[r][cc] = v;
        }
        __syncthreads();

        #pragma unroll
        for (int k = 0; k < 64; k += 4) {
            float4 a[4], b[2];
            #pragma unroll
            for (int i = 0; i < 4; ++i) a[i] = *(const float4*)&Xs[4 * w + i][k];
            b[0] = *(const float4*)&Wsm[l][k];
            b[1] = *(const float4*)&Wsm[l + 32][k];
            #pragma unroll
            for (int i = 0; i < 4; ++i) {
                #pragma unroll
                for (int m = 0; m < 2; ++m) {
                    c[i][m] = fmaf(a[i].x, b[m].x, c[i][m]);
                    c[i][m] = fmaf(a[i].y, b[m].y, c[i][m]);
                    c[i][m] = fmaf(a[i].z, b[m].z, c[i][m]);
                    c[i][m] = fmaf(a[i].w, b[m].w, c[i][m]);
                }
            }
        }
    }

    #pragma unroll
    for (int i = 0; i < 4; ++i) {
        g_q[(size_t)(m0 + 4 * w + i) * HDIM + l]      = c[i][0];
        g_q[(size_t)(m0 + 4 * w + i) * HDIM + l + 32] = c[i][1];
    }
}

// ---------------------------------------------------------------------------
// Causal flash attention with q = k = v.
// BM=32 query rows per CTA, BN=64 KV tile. grid = (64, BATCH), 256 threads.
// Warp w -> rows 4w..4w+3; lane l -> cols {l, l+32}. Heavy row-blocks first.
// S-GEMM:  A = Qs (uniform f4), B = Ks rows (stride-68 f4, conflict-free).
// PV-GEMM: A = Ps (uniform f4), B = Ks[k][col] (coalesced scalar).
// ---------------------------------------------------------------------------
__global__ __launch_bounds__(256) void attn_kernel(float* __restrict__ out)
{
    const int b     = 63 - (int)blockIdx.x;   // heavy blocks launch first
    const int batch = blockIdx.y;
    const float* qb = g_q + (size_t)batch * SEQ * HDIM;

    __shared__ float Qs[32][68];
    __shared__ float Ks[64][68];
    __shared__ float Ps[32][68];

    const int tid = threadIdx.x;
    const int w   = tid >> 5;   // rows 4w..4w+3 (uniform in warp)
    const int l   = tid & 31;   // cols {l, l+32}

    // Load Q tile: rows 32b..32b+31
    #pragma unroll
    for (int u = 0; u < 2; ++u) {
        const int f = u * 256 + tid;
        const int r = f >> 4;
        const int cc = (f & 15) << 2;
        float4 v = *(const float4*)(qb + (size_t)(32 * b + r) * HDIM + cc);
        *(float4*)&Qs[r][cc] = v;
    }

    float o[4][2] = {};
    float mrow[4], lrow[4];
    #pragma unroll
    for (int i = 0; i < 4; ++i) { mrow[i] = -CUDART_INF_F; lrow[i] = 0.0f; }

    const float scale  = 0.03125f;            // 1/sqrt(1024)
    const int   nTiles = (b >> 1) + 1;

    for (int kt = 0; kt < nTiles; ++kt) {
        __syncthreads();  // previous PV done reading Ks/Ps
        // Load K (=V) tile: rows 64kt..64kt+63
        #pragma unroll
        for (int u = 0; u < 4; ++u) {
            const int f = u * 256 + tid;
            const int r = f >> 4;
            const int cc = (f & 15) << 2;
            float4 v = *(const float4*)(qb + (size_t)(64 * kt + r) * HDIM + cc);
            *(float4*)&Ks[r][cc] = v;
        }
        __syncthreads();

        // S = Q @ K^T : s[i][m] = sum_k Q[4w+i][k] * K[l+32m][k]
        float s[4][2] = {};
        #pragma unroll
        for (int k = 0; k < 64; k += 4) {
            float4 a[4], kb[2];
            #pragma unroll
            for (int i = 0; i < 4; ++i) a[i] = *(const float4*)&Qs[4 * w + i][k];
            kb[0] = *(const float4*)&Ks[l][k];
            kb[1] = *(const float4*)&Ks[l + 32][k];
            #pragma unroll
            for (int i = 0; i < 4; ++i) {
                #pragma unroll
                for (int m = 0; m < 2; ++m) {
                    s[i][m] = fmaf(a[i].x, kb[m].x, s[i][m]);
                    s[i][m] = fmaf(a[i].y, kb[m].y, s[i][m]);
                    s[i][m] = fmaf(a[i].z, kb[m].z, s[i][m]);
                    s[i][m] = fmaf(a[i].w, kb[m].w, s[i][m]);
                }
            }
        }

        // scale + causal mask (only the last tile can touch the diagonal)
        if (kt == nTiles - 1) {
            #pragma unroll
            for (int i = 0; i < 4; ++i) {
                const int row_g = 32 * b + 4 * w + i;
                #pragma unroll
                for (int m = 0; m < 2; ++m) {
                    const int col_g = 64 * kt + l + 32 * m;
                    s[i][m] = (col_g > row_g) ? -CUDART_INF_F : s[i][m] * scale;
                }
            }
        } else {
            #pragma unroll
            for (int i = 0; i < 4; ++i)
                #pragma unroll
                for (int m = 0; m < 2; ++m)
                    s[i][m] *= scale;
        }

        // Online softmax — each row spans the full warp (32 lanes x 2 chunks)
        #pragma unroll
        for (int i = 0; i < 4; ++i) {
            float cm = fmaxf(s[i][0], s[i][1]);
            #pragma unroll
            for (int off = 16; off > 0; off >>= 1)
                cm = fmaxf(cm, __shfl_xor_sync(0xffffffffu, cm, off));
            const float mn    = fmaxf(mrow[i], cm);
            const float alpha = __expf(mrow[i] - mn);  // 0 if mrow was -inf
            mrow[i] = mn;

            s[i][0] = __expf(s[i][0] - mn);            // exp(-inf)=0 handles mask
            s[i][1] = __expf(s[i][1] - mn);
            float rs = s[i][0] + s[i][1];
            #pragma unroll
            for (int off = 16; off > 0; off >>= 1)
                rs += __shfl_xor_sync(0xffffffffu, rs, off);
            lrow[i] = lrow[i] * alpha + rs;
            o[i][0] *= alpha;
            o[i][1] *= alpha;
        }

        // Stage P (conflict-free: lanes write consecutive cols)
        #pragma unroll
        for (int i = 0; i < 4; ++i) {
            Ps[4 * w + i][l]      = s[i][0];
            Ps[4 * w + i][l + 32] = s[i][1];
        }
        __syncthreads();

        // O += P @ V  (V == Ks, layout [key][dim])
        #pragma unroll
        for (int kb = 0; kb < 64; kb += 4) {
            float4 pa[4];
            #pragma unroll
            for (int i = 0; i < 4; ++i) pa[i] = *(const float4*)&Ps[4 * w + i][kb];
            #pragma unroll
            for (int kk = 0; kk < 4; ++kk) {
                const float v0 = Ks[kb + kk][l];
                const float v1 = Ks[kb + kk][l + 32];
                #pragma unroll
                for (int i = 0; i < 4; ++i) {
                    const float av = (kk == 0) ? pa[i].x :
                                     (kk == 1) ? pa[i].y :
                                     (kk == 2) ? pa[i].z : pa[i].w;
                    o[i][0] = fmaf(av, v0, o[i][0]);
                    o[i][1] = fmaf(av, v1, o[i][1]);
                }
            }
        }
    }

    // Epilogue: normalize and store (coalesced)
    #pragma unroll
    for (int i = 0; i < 4; ++i) {
        const float inv = 1.0f / lrow[i];
        const size_t row = (size_t)batch * SEQ + 32 * b + 4 * w + i;
        out[row * HDIM + l]      = o[i][0] * inv;
        out[row * HDIM + l + 32] = o[i][1] * inv;
    }
}

extern "C" void kernel_launch(void* const* d_in, const int* in_sizes, int n_in,
                              void* d_out, int out_size)
{
    const float* x  = (const float*)d_in[0];   // [B, L, D] fp32
    const float* Wq = (const float*)d_in[1];   // [H, D] fp32
    float* out = (float*)d_out;                // [B, L, H] fp32

    proj_kernel<<<(BATCH * SEQ) / 32, 256>>>(x, Wq);
    dim3 grid(SEQ / 32, BATCH);
    attn_kernel<<<grid, 256>>>(out);
}